// round 12
// baseline (speedup 1.0000x reference)
#include <cuda_runtime.h>
#include <cstdint>

// TemporalCompressor: per-batch centered-window linear interpolation resample.
// encoded: [B, D, T] f32, ratio: [B] f32, out: [B, D, To] f32
//
// Final form (best measured: 91.4us ncu, DRAM 81% = mixed-R/W ceiling):
// 4 blocks per (b, d) row, each owning 1024 consecutive outputs.
// Input sub-window (<=8.2 KB) staged into SMEM with ONE cp.async.bulk +
// mbarrier (init + issue by thread 0, ONE syncthreads, then wait);
// interpolate from SMEM with exact per-element fma indexing (rel_err ~3e-6);
// float4 streaming stores. 16 CTAs/SM.

static constexpr int B_   = 32;
static constexpr int D_   = 512;
static constexpr int T_   = 8192;
static constexpr int TO_  = 4096;
static constexpr int NT   = 128;           // threads per block
static constexpr int NC   = 4;             // chunks per row
static constexpr int C_   = TO_ / NC;      // 1024 outputs per block
static constexpr int V4   = C_ / (NT * 4); // 2 float4 groups per thread
static constexpr int SBUF = C_ * 2 + 8;    // max window floats (2050) + pad

__global__ __launch_bounds__(NT, 16)
void temporal_compressor_kernel(const float* __restrict__ encoded,
                                const float* __restrict__ ratio,
                                float* __restrict__ out)
{
    __shared__ __align__(16) float buf[SBUF];              // 8.26 KB input tile
    __shared__ __align__(8)  unsigned long long mbar;

    const int chunk = blockIdx.x;          // 0..NC-1
    const int d     = blockIdx.y;
    const int b     = blockIdx.z;
    const int tid   = threadIdx.x;

    // Per-batch window parameters (uniform across block)
    const float r = __ldg(&ratio[b]);
    float Lf = floorf((float)TO_ * r);     // fp32 floor, exactly like reference
    int   L  = (int)Lf;
    if (L > T_) { L = T_; Lf = (float)T_; }
    const int   start = (T_ - L) >> 1;
    const float scale = Lf * (1.0f / (float)TO_);
    const float Lm1f  = (float)(L - 1);
    const int   Lm1   = L - 1;

    const int i0 = chunk * C_;

    // Source sub-window [g0, g1] (window-relative) needed by outputs
    // [i0, i0+C_), computed with the SAME clamped expression as the interp
    // loop (x is monotonic in i, so endpoints bound everything between).
    float x0 = fmaf((float)i0 + 0.5f, scale, -0.5f);
    x0 = fminf(fmaxf(x0, 0.0f), Lm1f);
    const int g0 = (int)x0;
    float x1 = fmaf((float)(i0 + C_ - 1) + 0.5f, scale, -0.5f);
    x1 = fminf(fmaxf(x1, 0.0f), Lm1f);
    const int g1 = min((int)x1 + 1, Lm1);

    // Absolute row offset of window start; align DOWN to 16B within the row.
    // Row base (multiple of T_ floats) is 16B-aligned, so row+aligned_g is too.
    const int s0        = start + g0;
    const int aligned_g = s0 & ~3;
    const int off       = s0 - aligned_g;              // 0..3
    int len = ((off + (g1 - g0 + 1) + 3) >> 2) << 2;   // round up to 4 floats
    if (aligned_g + len > T_) len = T_ - aligned_g;    // row clamp (keeps %4)

    const float* __restrict__ grow = encoded + ((size_t)b * D_ + d) * T_ + aligned_g;
    float* __restrict__ dst        = out     + ((size_t)b * D_ + d) * TO_;

    // ---- Stage sub-window into SMEM via one TMA bulk copy ----
    // Thread 0 inits the mbarrier AND issues the load; the single
    // __syncthreads below orders init before every thread's try_wait.
    const uint32_t mbar_addr = (uint32_t)__cvta_generic_to_shared(&mbar);
    const uint32_t sbuf_addr = (uint32_t)__cvta_generic_to_shared(buf);
    const uint32_t bytes     = (uint32_t)len * 4u;

    if (tid == 0) {
        asm volatile("mbarrier.init.shared.b64 [%0], %1;"
                     :: "r"(mbar_addr), "r"(1) : "memory");
        asm volatile("mbarrier.arrive.expect_tx.shared.b64 _, [%0], %1;"
                     :: "r"(mbar_addr), "r"(bytes) : "memory");
        asm volatile("cp.async.bulk.shared::cta.global.mbarrier::complete_tx::bytes "
                     "[%0], [%1], %2, [%3];"
                     :: "r"(sbuf_addr), "l"(grow), "r"(bytes), "r"(mbar_addr)
                     : "memory");
    }
    __syncthreads();
    // All threads wait on the mbarrier (parity 0; smem is fresh every launch)
    {
        uint32_t done;
        do {
            asm volatile(
                "{\n\t.reg .pred p;\n\t"
                "mbarrier.try_wait.parity.acquire.cta.shared::cta.b64 p, [%1], %2, 0x989680;\n\t"
                "selp.b32 %0, 1, 0, p;\n\t}"
                : "=r"(done) : "r"(mbar_addr), "r"(0u) : "memory");
        } while (!done);
    }

    // buf[k] = row[aligned_g + k]  ->  window[idx] = buf[idx - g0 + off]
    const int base = off - g0;

    // ---- Interpolate from SMEM, float4 streaming stores ----
#pragma unroll
    for (int v = 0; v < V4; ++v) {
        const int i_base = i0 + (tid + v * NT) * 4;
        float res[4];
#pragma unroll
        for (int k = 0; k < 4; ++k) {
            const int i = i_base + k;
            // Exact per-element index math (matches reference to ~3e-6)
            float x = fmaf((float)i + 0.5f, scale, -0.5f);
            x = fminf(fmaxf(x, 0.0f), Lm1f);
            const int   lo = (int)x;                 // x >= 0 -> trunc == floor
            const int   hi = min(lo + 1, Lm1);
            const float w  = x - (float)lo;
            const float g_lo = buf[base + lo];
            const float g_hi = buf[base + hi];
            res[k] = fmaf(g_hi - g_lo, w, g_lo);     // g_lo*(1-w) + g_hi*w
        }
        __stcs(reinterpret_cast<float4*>(dst + i_base),
               make_float4(res[0], res[1], res[2], res[3]));
    }
}

extern "C" void kernel_launch(void* const* d_in, const int* in_sizes, int n_in,
                              void* d_out, int out_size)
{
    const float* encoded = (const float*)d_in[0];
    const float* ratio   = (const float*)d_in[1];
    float* out           = (float*)d_out;

    dim3 block(NT, 1, 1);
    dim3 grid(NC, D_, B_);   // (4, 512, 32) = 65536 blocks
    temporal_compressor_kernel<<<grid, block>>>(encoded, ratio, out);
}

// round 13
// speedup vs baseline: 1.0066x; 1.0066x over previous
#include <cuda_runtime.h>
#include <cstdint>

// TemporalCompressor: per-batch centered-window linear interpolation resample.
// encoded: [B, D, T] f32, ratio: [B] f32, out: [B, D, To] f32
//
// Final form (best measured: 91.3us ncu, DRAM 81% = mixed-R/W ceiling):
// 4 blocks per (b, d) row, each owning 1024 consecutive outputs.
// Input sub-window (<=8.2 KB) staged into SMEM with ONE cp.async.bulk +
// mbarrier, tagged L2::evict_first (lines are read exactly once, so they
// should not compete with the write stream for L2 residency);
// interpolate from SMEM with exact per-element fma indexing (rel_err ~3e-6);
// float4 streaming stores. 16 CTAs/SM.

static constexpr int B_   = 32;
static constexpr int D_   = 512;
static constexpr int T_   = 8192;
static constexpr int TO_  = 4096;
static constexpr int NT   = 128;           // threads per block
static constexpr int NC   = 4;             // chunks per row
static constexpr int C_   = TO_ / NC;      // 1024 outputs per block
static constexpr int V4   = C_ / (NT * 4); // 2 float4 groups per thread
static constexpr int SBUF = C_ * 2 + 8;    // max window floats (2050) + pad

__global__ __launch_bounds__(NT, 16)
void temporal_compressor_kernel(const float* __restrict__ encoded,
                                const float* __restrict__ ratio,
                                float* __restrict__ out)
{
    __shared__ __align__(16) float buf[SBUF];              // 8.26 KB input tile
    __shared__ __align__(8)  unsigned long long mbar;

    const int chunk = blockIdx.x;          // 0..NC-1
    const int d     = blockIdx.y;
    const int b     = blockIdx.z;
    const int tid   = threadIdx.x;

    // Per-batch window parameters (uniform across block)
    const float r = __ldg(&ratio[b]);
    float Lf = floorf((float)TO_ * r);     // fp32 floor, exactly like reference
    int   L  = (int)Lf;
    if (L > T_) { L = T_; Lf = (float)T_; }
    const int   start = (T_ - L) >> 1;
    const float scale = Lf * (1.0f / (float)TO_);
    const float Lm1f  = (float)(L - 1);
    const int   Lm1   = L - 1;

    const int i0 = chunk * C_;

    // Source sub-window [g0, g1] (window-relative) needed by outputs
    // [i0, i0+C_), computed with the SAME clamped expression as the interp
    // loop (x is monotonic in i, so endpoints bound everything between).
    float x0 = fmaf((float)i0 + 0.5f, scale, -0.5f);
    x0 = fminf(fmaxf(x0, 0.0f), Lm1f);
    const int g0 = (int)x0;
    float x1 = fmaf((float)(i0 + C_ - 1) + 0.5f, scale, -0.5f);
    x1 = fminf(fmaxf(x1, 0.0f), Lm1f);
    const int g1 = min((int)x1 + 1, Lm1);

    // Absolute row offset of window start; align DOWN to 16B within the row.
    // Row base (multiple of T_ floats) is 16B-aligned, so row+aligned_g is too.
    const int s0        = start + g0;
    const int aligned_g = s0 & ~3;
    const int off       = s0 - aligned_g;              // 0..3
    int len = ((off + (g1 - g0 + 1) + 3) >> 2) << 2;   // round up to 4 floats
    if (aligned_g + len > T_) len = T_ - aligned_g;    // row clamp (keeps %4)

    const float* __restrict__ grow = encoded + ((size_t)b * D_ + d) * T_ + aligned_g;
    float* __restrict__ dst        = out     + ((size_t)b * D_ + d) * TO_;

    // ---- Stage sub-window into SMEM via one TMA bulk copy ----
    // Thread 0 inits the mbarrier AND issues the load; the single
    // __syncthreads below orders init before every thread's try_wait.
    const uint32_t mbar_addr = (uint32_t)__cvta_generic_to_shared(&mbar);
    const uint32_t sbuf_addr = (uint32_t)__cvta_generic_to_shared(buf);
    const uint32_t bytes     = (uint32_t)len * 4u;

    if (tid == 0) {
        asm volatile("mbarrier.init.shared.b64 [%0], %1;"
                     :: "r"(mbar_addr), "r"(1) : "memory");
        asm volatile("mbarrier.arrive.expect_tx.shared.b64 _, [%0], %1;"
                     :: "r"(mbar_addr), "r"(bytes) : "memory");
        asm volatile(
            "{\n\t"
            ".reg .b64 pol;\n\t"
            "createpolicy.fractional.L2::evict_first.b64 pol, 1.0;\n\t"
            "cp.async.bulk.shared::cta.global.mbarrier::complete_tx::bytes.L2::cache_hint "
            "[%0], [%1], %2, [%3], pol;\n\t"
            "}"
            :: "r"(sbuf_addr), "l"(grow), "r"(bytes), "r"(mbar_addr)
            : "memory");
    }
    __syncthreads();
    // All threads wait on the mbarrier (parity 0; smem is fresh every launch)
    {
        uint32_t done;
        do {
            asm volatile(
                "{\n\t.reg .pred p;\n\t"
                "mbarrier.try_wait.parity.acquire.cta.shared::cta.b64 p, [%1], %2, 0x989680;\n\t"
                "selp.b32 %0, 1, 0, p;\n\t}"
                : "=r"(done) : "r"(mbar_addr), "r"(0u) : "memory");
        } while (!done);
    }

    // buf[k] = row[aligned_g + k]  ->  window[idx] = buf[idx - g0 + off]
    const int base = off - g0;

    // ---- Interpolate from SMEM, float4 streaming stores ----
#pragma unroll
    for (int v = 0; v < V4; ++v) {
        const int i_base = i0 + (tid + v * NT) * 4;
        float res[4];
#pragma unroll
        for (int k = 0; k < 4; ++k) {
            const int i = i_base + k;
            // Exact per-element index math (matches reference to ~3e-6)
            float x = fmaf((float)i + 0.5f, scale, -0.5f);
            x = fminf(fmaxf(x, 0.0f), Lm1f);
            const int   lo = (int)x;                 // x >= 0 -> trunc == floor
            const int   hi = min(lo + 1, Lm1);
            const float w  = x - (float)lo;
            const float g_lo = buf[base + lo];
            const float g_hi = buf[base + hi];
            res[k] = fmaf(g_hi - g_lo, w, g_lo);     // g_lo*(1-w) + g_hi*w
        }
        __stcs(reinterpret_cast<float4*>(dst + i_base),
               make_float4(res[0], res[1], res[2], res[3]));
    }
}

extern "C" void kernel_launch(void* const* d_in, const int* in_sizes, int n_in,
                              void* d_out, int out_size)
{
    const float* encoded = (const float*)d_in[0];
    const float* ratio   = (const float*)d_in[1];
    float* out           = (float*)d_out;

    dim3 block(NT, 1, 1);
    dim3 grid(NC, D_, B_);   // (4, 512, 32) = 65536 blocks
    temporal_compressor_kernel<<<grid, block>>>(encoded, ratio, out);
}